// round 1
// baseline (speedup 1.0000x reference)
#include <cuda_runtime.h>
#include <math.h>

#define B_  2
#define C_  64
#define T_  3000
#define F_  65
#define H_  4
#define D_  4
#define E_  16
#define DF  260        // D*F
#define DFP 272        // padded to multiple of 16
#define EF  1040       // E*F
#define BH  8          // B*H
#define EPS 1e-5f

// ---------- scratch (static device globals: allowed; runtime alloc is not) ----
__device__ float g_Q[(size_t)BH * T_ * DFP];          // ~26 MB
__device__ float g_K[(size_t)BH * T_ * DFP];          // ~26 MB
__device__ float g_V[(size_t)BH * T_ * EF];           // ~100 MB
__device__ float g_S[(size_t)BH * T_ * T_];           // 288 MB
__device__ float g_O[(size_t)BH * T_ * EF];           // ~100 MB

// ---------- packed f32x2 helpers (FFMA2: 2x fp32 FMA throughput on sm_103a) --
__device__ __forceinline__ unsigned long long pk2(float lo, float hi) {
    unsigned long long r;
    asm("mov.b64 %0, {%1,%2};" : "=l"(r) : "f"(lo), "f"(hi));
    return r;
}
__device__ __forceinline__ void ffma2(unsigned long long& d,
                                      unsigned long long a,
                                      unsigned long long b) {
    asm("fma.rn.f32x2 %0, %1, %2, %0;" : "+l"(d) : "l"(a), "l"(b));
}

// ============================================================================
// Kernel 1: per-point Q/K/V 1x1-conv + PReLU + channel-LN.
// One thread = one (b,t,f) point. LN over D (or E) lives inside the thread.
// ============================================================================
__global__ void k_proj(const float* __restrict__ x,
                       const float* __restrict__ Wq, const float* __restrict__ bq,
                       const float* __restrict__ aq, const float* __restrict__ gq,
                       const float* __restrict__ betaq,
                       const float* __restrict__ Wk, const float* __restrict__ bk,
                       const float* __restrict__ ak, const float* __restrict__ gk,
                       const float* __restrict__ betak,
                       const float* __restrict__ Wv, const float* __restrict__ bv,
                       const float* __restrict__ av, const float* __restrict__ gv,
                       const float* __restrict__ betav) {
    __shared__ float sWq[H_ * D_ * C_];
    __shared__ float sWk[H_ * D_ * C_];
    __shared__ float sWv[H_ * E_ * C_];
    int tid = threadIdx.x;
    for (int i = tid; i < H_ * D_ * C_; i += blockDim.x) { sWq[i] = Wq[i]; sWk[i] = Wk[i]; }
    for (int i = tid; i < H_ * E_ * C_; i += blockDim.x) sWv[i] = Wv[i];
    __syncthreads();

    int p = blockIdx.x * blockDim.x + tid;
    const int P = B_ * T_ * F_;
    if (p >= P) return;
    int b = p / (T_ * F_);
    int r = p % (T_ * F_);
    int t = r / F_;
    int f = r % F_;

    float xv[C_];
#pragma unroll
    for (int c = 0; c < C_; c++)
        xv[c] = x[((size_t)(b * C_ + c) * T_ + t) * F_ + f];

    for (int h = 0; h < H_; h++) {
        // ---- Q ----
        {
            float q[D_];
            float ah = aq[h];
#pragma unroll
            for (int d = 0; d < D_; d++) {
                float acc = bq[h * D_ + d];
#pragma unroll
                for (int c = 0; c < C_; c++) acc += sWq[(h * D_ + d) * C_ + c] * xv[c];
                q[d] = acc >= 0.f ? acc : ah * acc;
            }
            float mu = 0.f, s2 = 0.f;
#pragma unroll
            for (int d = 0; d < D_; d++) { mu += q[d]; s2 += q[d] * q[d]; }
            mu *= (1.f / D_);
            s2 = s2 * (1.f / D_) - mu * mu;
            float inv = rsqrtf(s2 + EPS);
            size_t row = ((size_t)(b * H_ + h) * T_ + t) * DFP;
#pragma unroll
            for (int d = 0; d < D_; d++)
                g_Q[row + d * F_ + f] = (q[d] - mu) * inv * gq[h * D_ + d] + betaq[h * D_ + d];
            if (f < DFP - DF) g_Q[row + DF + f] = 0.f;   // zero the K-dim pad
        }
        // ---- K ----
        {
            float q[D_];
            float ah = ak[h];
#pragma unroll
            for (int d = 0; d < D_; d++) {
                float acc = bk[h * D_ + d];
#pragma unroll
                for (int c = 0; c < C_; c++) acc += sWk[(h * D_ + d) * C_ + c] * xv[c];
                q[d] = acc >= 0.f ? acc : ah * acc;
            }
            float mu = 0.f, s2 = 0.f;
#pragma unroll
            for (int d = 0; d < D_; d++) { mu += q[d]; s2 += q[d] * q[d]; }
            mu *= (1.f / D_);
            s2 = s2 * (1.f / D_) - mu * mu;
            float inv = rsqrtf(s2 + EPS);
            size_t row = ((size_t)(b * H_ + h) * T_ + t) * DFP;
#pragma unroll
            for (int d = 0; d < D_; d++)
                g_K[row + d * F_ + f] = (q[d] - mu) * inv * gk[h * D_ + d] + betak[h * D_ + d];
            if (f < DFP - DF) g_K[row + DF + f] = 0.f;
        }
        // ---- V ----
        {
            float v[E_];
            float ah = av[h];
#pragma unroll
            for (int e = 0; e < E_; e++) {
                float acc = bv[h * E_ + e];
#pragma unroll
                for (int c = 0; c < C_; c++) acc += sWv[(h * E_ + e) * C_ + c] * xv[c];
                v[e] = acc >= 0.f ? acc : ah * acc;
            }
            float mu = 0.f, s2 = 0.f;
#pragma unroll
            for (int e = 0; e < E_; e++) { mu += v[e]; s2 += v[e] * v[e]; }
            mu *= (1.f / E_);
            s2 = s2 * (1.f / E_) - mu * mu;
            float inv = rsqrtf(s2 + EPS);
            size_t row = ((size_t)(b * H_ + h) * T_ + t) * EF;
#pragma unroll
            for (int e = 0; e < E_; e++)
                g_V[row + e * F_ + f] = (v[e] - mu) * inv * gv[h * E_ + e] + betav[h * E_ + e];
        }
    }
}

// ============================================================================
// Kernel 2: S = scale * Q @ K^T.  64x64 tiles, BK=16, 4x4 micro-tiles, FFMA2.
// ============================================================================
__global__ void k_qk() {
    __shared__ float As[16][64];   // As[k][m]
    __shared__ float Bs[16][64];   // Bs[k][n]
    int bh = blockIdx.z;
    int m0 = blockIdx.y * 64;
    int n0 = blockIdx.x * 64;
    int tid = threadIdx.x;         // 256
    int lrow = tid >> 2;           // 0..63
    int lcol = (tid & 3) * 4;      // 0,4,8,12
    int tm = tid >> 4, tn = tid & 15;

    const float* A  = g_Q + (size_t)bh * T_ * DFP;
    const float* Bm = g_K + (size_t)bh * T_ * DFP;

    unsigned long long acc[4][2];
#pragma unroll
    for (int i = 0; i < 4; i++) { acc[i][0] = 0ull; acc[i][1] = 0ull; }

    for (int k0 = 0; k0 < DFP; k0 += 16) {
        float4 a4 = make_float4(0.f, 0.f, 0.f, 0.f);
        float4 b4 = make_float4(0.f, 0.f, 0.f, 0.f);
        int am = m0 + lrow;
        if (am < T_) a4 = *reinterpret_cast<const float4*>(&A[(size_t)am * DFP + k0 + lcol]);
        int bn = n0 + lrow;
        if (bn < T_) b4 = *reinterpret_cast<const float4*>(&Bm[(size_t)bn * DFP + k0 + lcol]);
        __syncthreads();
        As[lcol + 0][lrow] = a4.x; As[lcol + 1][lrow] = a4.y;
        As[lcol + 2][lrow] = a4.z; As[lcol + 3][lrow] = a4.w;
        Bs[lcol + 0][lrow] = b4.x; Bs[lcol + 1][lrow] = b4.y;
        Bs[lcol + 2][lrow] = b4.z; Bs[lcol + 3][lrow] = b4.w;
        __syncthreads();
#pragma unroll
        for (int kk = 0; kk < 16; kk++) {
            float4 av4 = *reinterpret_cast<const float4*>(&As[kk][tm * 4]);
            const unsigned long long* bp =
                reinterpret_cast<const unsigned long long*>(&Bs[kk][tn * 4]);
            unsigned long long b0 = bp[0], b1 = bp[1];
            const float* af = &av4.x;
#pragma unroll
            for (int i = 0; i < 4; i++) {
                unsigned long long ap = pk2(af[i], af[i]);
                ffma2(acc[i][0], ap, b0);
                ffma2(acc[i][1], ap, b1);
            }
        }
    }

    const float scale = 1.0f / sqrtf((float)DF);
    float* S = g_S + (size_t)bh * T_ * T_;
#pragma unroll
    for (int i = 0; i < 4; i++) {
        int m = m0 + tm * 4 + i;
        if (m >= T_) continue;
#pragma unroll
        for (int pp = 0; pp < 2; pp++) {
            int n = n0 + tn * 4 + pp * 2;
            if (n >= T_) continue;
            float2 v = *reinterpret_cast<float2*>(&acc[i][pp]);
            float2 o; o.x = v.x * scale; o.y = v.y * scale;
            *reinterpret_cast<float2*>(&S[(size_t)m * T_ + n]) = o;
        }
    }
}

// ============================================================================
// Kernel 3: in-place row softmax of S. One CTA per row; row cached in smem.
// ============================================================================
__global__ void k_softmax() {
    __shared__ float buf[T_];
    __shared__ float red[33];
    size_t row = blockIdx.x;
    float* S = g_S + row * (size_t)T_;
    int tid = threadIdx.x;   // 256

    float mx = -3.4e38f;
    for (int i = tid; i < T_; i += 256) { float v = S[i]; buf[i] = v; mx = fmaxf(mx, v); }
#pragma unroll
    for (int o = 16; o; o >>= 1) mx = fmaxf(mx, __shfl_xor_sync(~0u, mx, o));
    if ((tid & 31) == 0) red[tid >> 5] = mx;
    __syncthreads();
    if (tid < 32) {
        float v = (tid < 8) ? red[tid] : -3.4e38f;
#pragma unroll
        for (int o = 4; o; o >>= 1) v = fmaxf(v, __shfl_xor_sync(~0u, v, o));
        if (tid == 0) red[32] = v;
    }
    __syncthreads();
    mx = red[32];

    float sum = 0.f;
    for (int i = tid; i < T_; i += 256) { float e = __expf(buf[i] - mx); buf[i] = e; sum += e; }
#pragma unroll
    for (int o = 16; o; o >>= 1) sum += __shfl_xor_sync(~0u, sum, o);
    if ((tid & 31) == 0) red[tid >> 5] = sum;
    __syncthreads();
    if (tid < 32) {
        float v = (tid < 8) ? red[tid] : 0.f;
#pragma unroll
        for (int o = 4; o; o >>= 1) v += __shfl_xor_sync(~0u, v, o);
        if (tid == 0) red[32] = v;
    }
    __syncthreads();
    float inv = 1.f / red[32];
    for (int i = tid; i < T_; i += 256) S[i] = buf[i] * inv;
}

// ============================================================================
// Kernel 4: O = P @ V.  M=3000, N=1040, K=3000. Same FFMA2 micro-kernel.
// ============================================================================
__global__ void k_pv() {
    __shared__ float As[16][64];   // P^T tile: As[k][m]
    __shared__ float Bs[16][64];   // V tile:   Bs[k][n]
    int bh = blockIdx.z;
    int m0 = blockIdx.y * 64;
    int n0 = blockIdx.x * 64;
    int tid = threadIdx.x;
    int tm = tid >> 4, tn = tid & 15;

    const float* A  = g_S + (size_t)bh * T_ * T_;
    const float* Bm = g_V + (size_t)bh * T_ * EF;
    float*       Om = g_O + (size_t)bh * T_ * EF;

    int arow = tid >> 2;        // 0..63 (m)
    int acol = (tid & 3) * 4;   // 0,4,8,12 (k)
    int brow = tid >> 4;        // 0..15 (k)
    int bcolg = (tid & 15) * 4; // 0..60 (n)

    unsigned long long acc[4][2];
#pragma unroll
    for (int i = 0; i < 4; i++) { acc[i][0] = 0ull; acc[i][1] = 0ull; }

    for (int k0 = 0; k0 < T_; k0 += 16) {
        float4 a4 = make_float4(0.f, 0.f, 0.f, 0.f);
        float4 b4 = make_float4(0.f, 0.f, 0.f, 0.f);
        int am = m0 + arow, akk = k0 + acol;
        if (am < T_ && akk < T_)
            a4 = *reinterpret_cast<const float4*>(&A[(size_t)am * T_ + akk]);
        int bk = k0 + brow, bn = n0 + bcolg;
        if (bk < T_ && bn < EF)
            b4 = *reinterpret_cast<const float4*>(&Bm[(size_t)bk * EF + bn]);
        __syncthreads();
        As[acol + 0][arow] = a4.x; As[acol + 1][arow] = a4.y;
        As[acol + 2][arow] = a4.z; As[acol + 3][arow] = a4.w;
        *reinterpret_cast<float4*>(&Bs[brow][bcolg]) = b4;
        __syncthreads();
#pragma unroll
        for (int kk = 0; kk < 16; kk++) {
            float4 av4 = *reinterpret_cast<const float4*>(&As[kk][tm * 4]);
            const unsigned long long* bp =
                reinterpret_cast<const unsigned long long*>(&Bs[kk][tn * 4]);
            unsigned long long b0 = bp[0], b1 = bp[1];
            const float* af = &av4.x;
#pragma unroll
            for (int i = 0; i < 4; i++) {
                unsigned long long ap = pk2(af[i], af[i]);
                ffma2(acc[i][0], ap, b0);
                ffma2(acc[i][1], ap, b1);
            }
        }
    }

#pragma unroll
    for (int i = 0; i < 4; i++) {
        int m = m0 + tm * 4 + i;
        if (m >= T_) continue;
#pragma unroll
        for (int pp = 0; pp < 2; pp++) {
            int n = n0 + tn * 4 + pp * 2;
            if (n >= EF) continue;
            *reinterpret_cast<float2*>(&Om[(size_t)m * EF + n]) =
                *reinterpret_cast<float2*>(&acc[i][pp]);
        }
    }
}

// ============================================================================
// Kernel 5: final 1x1 conv (64x64) + PReLU + channel-LN + residual.
// One thread = one (b,t,f) point.
// ============================================================================
__global__ void k_final(const float* __restrict__ x,
                        const float* __restrict__ Wp, const float* __restrict__ bp,
                        const float* __restrict__ ap, const float* __restrict__ gp,
                        const float* __restrict__ betap,
                        float* __restrict__ out) {
    __shared__ float sW[C_ * C_];
    int tid = threadIdx.x;
    for (int i = tid; i < C_ * C_; i += blockDim.x) sW[i] = Wp[i];
    __syncthreads();

    int p = blockIdx.x * blockDim.x + tid;
    const int P = B_ * T_ * F_;
    if (p >= P) return;
    int b = p / (T_ * F_);
    int r = p % (T_ * F_);
    int t = r / F_;
    int f = r % F_;

    float ov[C_];
#pragma unroll
    for (int c = 0; c < C_; c++) {
        int h = c >> 4, e = c & 15;
        ov[c] = g_O[((size_t)(b * H_ + h) * T_ + t) * EF + e * F_ + f];
    }

    float y[C_];
    float a = ap[0];
    float mu = 0.f, s2 = 0.f;
#pragma unroll 1
    for (int o = 0; o < C_; o++) {
        float acc = bp[o];
#pragma unroll
        for (int c = 0; c < C_; c++) acc += sW[o * C_ + c] * ov[c];
        acc = acc >= 0.f ? acc : a * acc;
        y[o] = acc;
        mu += acc;
        s2 += acc * acc;
    }
    mu *= (1.f / C_);
    s2 = s2 * (1.f / C_) - mu * mu;
    float inv = rsqrtf(s2 + EPS);
#pragma unroll 1
    for (int o = 0; o < C_; o++) {
        float val = (y[o] - mu) * inv * gp[o] + betap[o];
        size_t idx = ((size_t)(b * C_ + o) * T_ + t) * F_ + f;
        out[idx] = val + x[idx];
    }
}

// ============================================================================
extern "C" void kernel_launch(void* const* d_in, const int* in_sizes, int n_in,
                              void* d_out, int out_size) {
    const float* x     = (const float*)d_in[0];
    const float* Wq    = (const float*)d_in[1];
    const float* bq    = (const float*)d_in[2];
    const float* aq    = (const float*)d_in[3];
    const float* gq    = (const float*)d_in[4];
    const float* betaq = (const float*)d_in[5];
    const float* Wk    = (const float*)d_in[6];
    const float* bk    = (const float*)d_in[7];
    const float* ak    = (const float*)d_in[8];
    const float* gk    = (const float*)d_in[9];
    const float* betak = (const float*)d_in[10];
    const float* Wv    = (const float*)d_in[11];
    const float* bv    = (const float*)d_in[12];
    const float* av    = (const float*)d_in[13];
    const float* gv    = (const float*)d_in[14];
    const float* betav = (const float*)d_in[15];
    const float* Wp    = (const float*)d_in[16];
    const float* bp    = (const float*)d_in[17];
    const float* ap    = (const float*)d_in[18];
    const float* gp    = (const float*)d_in[19];
    const float* betap = (const float*)d_in[20];
    float* out = (float*)d_out;

    const int P = B_ * T_ * F_;
    k_proj<<<(P + 255) / 256, 256>>>(x, Wq, bq, aq, gq, betaq,
                                     Wk, bk, ak, gk, betak,
                                     Wv, bv, av, gv, betav);

    dim3 g2((T_ + 63) / 64, (T_ + 63) / 64, BH);
    k_qk<<<g2, 256>>>();

    k_softmax<<<BH * T_, 256>>>();

    dim3 g4((EF + 63) / 64, (T_ + 63) / 64, BH);
    k_pv<<<g4, 256>>>();

    k_final<<<(P + 127) / 128, 128>>>(x, Wp, bp, ap, gp, betap, out);
}

// round 3
// speedup vs baseline: 4.2977x; 4.2977x over previous
#include <cuda_runtime.h>
#include <cuda_fp16.h>
#include <math.h>
#include <cstdint>

#define B_    2
#define C_    64
#define T_    3000
#define F_    65
#define H_    4
#define D_    4
#define E_    16
#define DF    260
#define KQK   288      // QK K-dim padded (mult of 32)
#define EF    1040
#define NPV   1152     // PV N-dim padded (mult of 128)
#define KPV   3008     // PV K-dim padded (mult of 32)
#define TMPAD 3072     // M padded (mult of 128)
#define TNP   3072     // QK N padded
#define BH    8
#define EPS   1e-5f

// ---------------- scratch (zero-initialized .bss; pads rely on that + writes)
__device__ __align__(128) __half g_Qh[(size_t)BH * TMPAD * KQK];
__device__ __align__(128) __half g_Kh[(size_t)BH * TMPAD * KQK];
__device__ __align__(128) __half g_P [(size_t)BH * TMPAD * KPV];
__device__ __align__(128) __half g_Vn[(size_t)BH * KPV * NPV];
__device__ __align__(128) float  g_S [(size_t)BH * TMPAD * TNP];
__device__ __align__(128) float  g_O [(size_t)BH * T_ * EF];

// ---------------- helpers ----------------------------------------------------
__device__ __forceinline__ uint32_t smem_u32(const void* p) {
    uint32_t a;
    asm("{ .reg .u64 t; cvta.to.shared.u64 t, %1; cvt.u32.u64 %0, t; }" : "=r"(a) : "l"(p));
    return a;
}
__device__ __forceinline__ void cpa16(uint32_t s, const void* g) {
    asm volatile("cp.async.cg.shared.global [%0], [%1], 16;" :: "r"(s), "l"(g));
}
__device__ __forceinline__ void ldm4(uint32_t* r, uint32_t a) {
    asm volatile("ldmatrix.sync.aligned.m8n8.x4.shared.b16 {%0,%1,%2,%3}, [%4];"
                 : "=r"(r[0]), "=r"(r[1]), "=r"(r[2]), "=r"(r[3]) : "r"(a));
}
__device__ __forceinline__ void ldm4t(uint32_t* r, uint32_t a) {
    asm volatile("ldmatrix.sync.aligned.m8n8.x4.trans.shared.b16 {%0,%1,%2,%3}, [%4];"
                 : "=r"(r[0]), "=r"(r[1]), "=r"(r[2]), "=r"(r[3]) : "r"(a));
}
__device__ __forceinline__ void mma16816(float* c, const uint32_t* a, const uint32_t* b) {
    asm volatile("mma.sync.aligned.m16n8k16.row.col.f32.f16.f16.f32 "
                 "{%0,%1,%2,%3}, {%4,%5,%6,%7}, {%8,%9}, {%0,%1,%2,%3};"
                 : "+f"(c[0]), "+f"(c[1]), "+f"(c[2]), "+f"(c[3])
                 : "r"(a[0]), "r"(a[1]), "r"(a[2]), "r"(a[3]), "r"(b[0]), "r"(b[1]));
}

// ============================================================================
// Kernel 1: Q/K/V 1x1-conv + PReLU + channel-LN -> fp16.
// Q,K: [bh][t][KQK] row-major (k-pad cols zeroed). V: [bh][t][NPV] natural.
// ============================================================================
__global__ void k_proj(const float* __restrict__ x,
                       const float* __restrict__ Wq, const float* __restrict__ bq,
                       const float* __restrict__ aq, const float* __restrict__ gq,
                       const float* __restrict__ betaq,
                       const float* __restrict__ Wk, const float* __restrict__ bk,
                       const float* __restrict__ ak, const float* __restrict__ gk,
                       const float* __restrict__ betak,
                       const float* __restrict__ Wv, const float* __restrict__ bv,
                       const float* __restrict__ av, const float* __restrict__ gv,
                       const float* __restrict__ betav) {
    __shared__ float sWq[H_ * D_ * C_];
    __shared__ float sWk[H_ * D_ * C_];
    __shared__ float sWv[H_ * E_ * C_];
    int tid = threadIdx.x;
    for (int i = tid; i < H_ * D_ * C_; i += blockDim.x) { sWq[i] = Wq[i]; sWk[i] = Wk[i]; }
    for (int i = tid; i < H_ * E_ * C_; i += blockDim.x) sWv[i] = Wv[i];
    __syncthreads();

    int p = blockIdx.x * blockDim.x + tid;
    const int P = B_ * T_ * F_;
    if (p >= P) return;
    int b = p / (T_ * F_);
    int r = p % (T_ * F_);
    int t = r / F_;
    int f = r % F_;

    float xv[C_];
#pragma unroll
    for (int c = 0; c < C_; c++)
        xv[c] = x[((size_t)(b * C_ + c) * T_ + t) * F_ + f];

    const __half hz = __float2half(0.0f);
    for (int h = 0; h < H_; h++) {
        int bh = b * H_ + h;
        // ---- Q ----
        {
            float q[D_];
            float ah = aq[h];
#pragma unroll
            for (int d = 0; d < D_; d++) {
                float acc = bq[h * D_ + d];
#pragma unroll
                for (int c = 0; c < C_; c++) acc += sWq[(h * D_ + d) * C_ + c] * xv[c];
                q[d] = acc >= 0.f ? acc : ah * acc;
            }
            float mu = 0.f, s2 = 0.f;
#pragma unroll
            for (int d = 0; d < D_; d++) { mu += q[d]; s2 += q[d] * q[d]; }
            mu *= (1.f / D_);
            s2 = s2 * (1.f / D_) - mu * mu;
            float inv = rsqrtf(s2 + EPS);
            size_t base = ((size_t)bh * TMPAD + t) * KQK;
#pragma unroll
            for (int d = 0; d < D_; d++)
                g_Qh[base + d * F_ + f] =
                    __float2half((q[d] - mu) * inv * gq[h * D_ + d] + betaq[h * D_ + d]);
            if (f < KQK - DF) g_Qh[base + DF + f] = hz;
        }
        // ---- K ----
        {
            float q[D_];
            float ah = ak[h];
#pragma unroll
            for (int d = 0; d < D_; d++) {
                float acc = bk[h * D_ + d];
#pragma unroll
                for (int c = 0; c < C_; c++) acc += sWk[(h * D_ + d) * C_ + c] * xv[c];
                q[d] = acc >= 0.f ? acc : ah * acc;
            }
            float mu = 0.f, s2 = 0.f;
#pragma unroll
            for (int d = 0; d < D_; d++) { mu += q[d]; s2 += q[d] * q[d]; }
            mu *= (1.f / D_);
            s2 = s2 * (1.f / D_) - mu * mu;
            float inv = rsqrtf(s2 + EPS);
            size_t base = ((size_t)bh * TMPAD + t) * KQK;
#pragma unroll
            for (int d = 0; d < D_; d++)
                g_Kh[base + d * F_ + f] =
                    __float2half((q[d] - mu) * inv * gk[h * D_ + d] + betak[h * D_ + d]);
            if (f < KQK - DF) g_Kh[base + DF + f] = hz;
        }
        // ---- V (natural layout [t][ef], transposed later inside the GEMM) ----
        {
            float v[E_];
            float ah = av[h];
#pragma unroll
            for (int e = 0; e < E_; e++) {
                float acc = bv[h * E_ + e];
#pragma unroll
                for (int c = 0; c < C_; c++) acc += sWv[(h * E_ + e) * C_ + c] * xv[c];
                v[e] = acc >= 0.f ? acc : ah * acc;
            }
            float mu = 0.f, s2 = 0.f;
#pragma unroll
            for (int e = 0; e < E_; e++) { mu += v[e]; s2 += v[e] * v[e]; }
            mu *= (1.f / E_);
            s2 = s2 * (1.f / E_) - mu * mu;
            float inv = rsqrtf(s2 + EPS);
            size_t base = ((size_t)bh * KPV + t) * NPV;
#pragma unroll
            for (int e = 0; e < E_; e++)
                g_Vn[base + e * F_ + f] =
                    __float2half((v[e] - mu) * inv * gv[h * E_ + e] + betav[h * E_ + e]);
        }
    }
}

// ============================================================================
// HMMA GEMM: D[m][n] = sum_k A[m][k] * B[.][.]
//   QK (PV=false): A=Q[m][k], B=K[n][k]   -> S = scale * (...)  fp32
//   PV (PV=true) : A=P[m][k], B=Vn[k][n]  -> O (fp32, guarded to [T_, EF])
// CTA 128x128, BK=32, 8 warps (warp 32x64), cp.async double buffer.
// A smem rows padded to 80B (conflict-free ldmatrix); PV-B rows padded to 272B.
// ============================================================================
#define ASTG 10240
#define BSTG 10240
#define STG  (ASTG + BSTG)

template <bool PV>
__global__ void __launch_bounds__(256, 2) k_gemm(float scale) {
    __shared__ __align__(128) char smem[2 * STG];
    const int tid = threadIdx.x;
    const int wid = tid >> 5, lane = tid & 31;
    const int wm = wid & 3, wn = wid >> 2;
    const int bh = blockIdx.z, m0 = blockIdx.y * 128, n0 = blockIdx.x * 128;

    const __half *Ag, *Bg;
    int lda, chunks;
    if (PV) {
        Ag = g_P + (size_t)bh * TMPAD * KPV;  lda = KPV;
        Bg = g_Vn + (size_t)bh * KPV * NPV;   chunks = KPV / 32;
    } else {
        Ag = g_Qh + (size_t)bh * TMPAD * KQK; lda = KQK;
        Bg = g_Kh + (size_t)bh * TMPAD * KQK; chunks = KQK / 32;
    }

    const uint32_t sbase = smem_u32(smem);

    float acc[2][8][4];
#pragma unroll
    for (int i = 0; i < 2; i++)
#pragma unroll
        for (int j = 0; j < 8; j++)
#pragma unroll
            for (int q = 0; q < 4; q++) acc[i][j][q] = 0.f;

    auto load_stage = [&](int st, int c) {
        uint32_t sa = sbase + st * STG;
        uint32_t sb = sa + ASTG;
        int k0 = c * 32;
#pragma unroll
        for (int j = 0; j < 2; j++) {
            int idx = tid * 2 + j;
            {   // A tile: 128 rows x 64B (4 granules), 80B smem stride
                int row = idx >> 2, g = idx & 3;
                cpa16(sa + row * 80 + g * 16, Ag + (size_t)(m0 + row) * lda + k0 + g * 8);
            }
            if (PV) {  // B tile: 32 k-rows x 256B (16 granules), 272B stride
                int row = idx >> 4, g = idx & 15;
                cpa16(sb + row * 272 + g * 16, Bg + (size_t)(k0 + row) * NPV + n0 + g * 8);
            } else {   // B tile: 128 n-rows x 64B, 80B stride
                int row = idx >> 2, g = idx & 3;
                cpa16(sb + row * 80 + g * 16, Bg + (size_t)(n0 + row) * lda + k0 + g * 8);
            }
        }
    };

    auto compute_stage = [&](int st) {
        uint32_t sa = sbase + st * STG;
        uint32_t sb = sa + ASTG;
#pragma unroll
        for (int kk = 0; kk < 32; kk += 16) {
            uint32_t a[2][4];
#pragma unroll
            for (int mt = 0; mt < 2; mt++) {
                int row = wm * 32 + mt * 16 + (lane & 15);
                ldm4(a[mt], sa + row * 80 + (kk + ((lane >> 4) << 3)) * 2);
            }
            uint32_t bfr[4][4];
#pragma unroll
            for (int bt = 0; bt < 4; bt++) {
                if (PV) {
                    int krow = kk + (lane & 15);
                    int ncol = wn * 64 + bt * 16 + ((lane >> 4) << 3);
                    ldm4t(bfr[bt], sb + krow * 272 + ncol * 2);
                } else {
                    int row = wn * 64 + bt * 16 + ((lane >> 4) << 3) + (lane & 7);
                    ldm4(bfr[bt], sb + row * 80 + (kk + ((lane >> 3) & 1) * 8) * 2);
                }
            }
#pragma unroll
            for (int mt = 0; mt < 2; mt++)
#pragma unroll
                for (int nt = 0; nt < 8; nt++)
                    mma16816(acc[mt][nt], a[mt], &bfr[nt >> 1][(nt & 1) * 2]);
        }
    };

    load_stage(0, 0);
    asm volatile("cp.async.commit_group;" ::: "memory");
    for (int c = 0; c < chunks; c++) {
        int st = c & 1;
        if (c + 1 < chunks) {
            load_stage(st ^ 1, c + 1);
            asm volatile("cp.async.commit_group;" ::: "memory");
            asm volatile("cp.async.wait_group 1;" ::: "memory");
        } else {
            asm volatile("cp.async.wait_group 0;" ::: "memory");
        }
        __syncthreads();
        compute_stage(st);
        __syncthreads();
    }

    // epilogue
#pragma unroll
    for (int mt = 0; mt < 2; mt++)
#pragma unroll
        for (int nt = 0; nt < 8; nt++) {
            int r0 = m0 + wm * 32 + mt * 16 + (lane >> 2);
            int cc = n0 + wn * 64 + nt * 8 + (lane & 3) * 2;
            float* a4 = acc[mt][nt];
            if (PV) {
                if (cc < EF) {
                    if (r0 < T_)
                        *reinterpret_cast<float2*>(&g_O[((size_t)bh * T_ + r0) * EF + cc]) =
                            make_float2(a4[0], a4[1]);
                    if (r0 + 8 < T_)
                        *reinterpret_cast<float2*>(&g_O[((size_t)bh * T_ + r0 + 8) * EF + cc]) =
                            make_float2(a4[2], a4[3]);
                }
            } else {
                *reinterpret_cast<float2*>(&g_S[((size_t)bh * TMPAD + r0) * TNP + cc]) =
                    make_float2(a4[0] * scale, a4[1] * scale);
                *reinterpret_cast<float2*>(&g_S[((size_t)bh * TMPAD + r0 + 8) * TNP + cc]) =
                    make_float2(a4[2] * scale, a4[3] * scale);
            }
        }
}

// ============================================================================
// Kernel 3: row softmax of S -> P fp16 (pad rows/cols zeroed).
// ============================================================================
__global__ void k_softmax() {
    __shared__ float buf[T_];
    __shared__ float red[33];
    int row = blockIdx.x, bh = blockIdx.y, tid = threadIdx.x;
    __half* Pr = g_P + ((size_t)bh * TMPAD + row) * KPV;
    const __half hz = __float2half(0.0f);
    if (row >= T_) {
        for (int i = tid; i < KPV; i += 256) Pr[i] = hz;
        return;
    }
    const float* S = g_S + ((size_t)bh * TMPAD + row) * TNP;

    float mx = -3.4e38f;
    for (int i = tid; i < T_; i += 256) { float v = S[i]; buf[i] = v; mx = fmaxf(mx, v); }
#pragma unroll
    for (int o = 16; o; o >>= 1) mx = fmaxf(mx, __shfl_xor_sync(~0u, mx, o));
    if ((tid & 31) == 0) red[tid >> 5] = mx;
    __syncthreads();
    if (tid < 32) {
        float v = (tid < 8) ? red[tid] : -3.4e38f;
#pragma unroll
        for (int o = 4; o; o >>= 1) v = fmaxf(v, __shfl_xor_sync(~0u, v, o));
        if (tid == 0) red[32] = v;
    }
    __syncthreads();
    mx = red[32];

    float sum = 0.f;
    for (int i = tid; i < T_; i += 256) { float e = __expf(buf[i] - mx); buf[i] = e; sum += e; }
#pragma unroll
    for (int o = 16; o; o >>= 1) sum += __shfl_xor_sync(~0u, sum, o);
    if ((tid & 31) == 0) red[tid >> 5] = sum;
    __syncthreads();
    if (tid < 32) {
        float v = (tid < 8) ? red[tid] : 0.f;
#pragma unroll
        for (int o = 4; o; o >>= 1) v += __shfl_xor_sync(~0u, v, o);
        if (tid == 0) red[32] = v;
    }
    __syncthreads();
    float inv = 1.f / red[32];
    for (int i = tid; i < T_; i += 256) Pr[i] = __float2half(buf[i] * inv);
    if (tid < KPV - T_) Pr[T_ + tid] = hz;
}

// ============================================================================
// Kernel 5: final 1x1 conv (64x64) + PReLU + channel-LN + residual.
// ============================================================================
__global__ void k_final(const float* __restrict__ x,
                        const float* __restrict__ Wp, const float* __restrict__ bp,
                        const float* __restrict__ ap, const float* __restrict__ gp,
                        const float* __restrict__ betap,
                        float* __restrict__ out) {
    __shared__ float sW[C_ * C_];
    int tid = threadIdx.x;
    for (int i = tid; i < C_ * C_; i += blockDim.x) sW[i] = Wp[i];
    __syncthreads();

    int p = blockIdx.x * blockDim.x + tid;
    const int P = B_ * T_ * F_;
    if (p >= P) return;
    int b = p / (T_ * F_);
    int r = p % (T_ * F_);
    int t = r / F_;
    int f = r % F_;

    float ov[C_];
#pragma unroll
    for (int c = 0; c < C_; c++) {
        int h = c >> 4, e = c & 15;
        ov[c] = g_O[((size_t)(b * H_ + h) * T_ + t) * EF + e * F_ + f];
    }

    float y[C_];
    float a = ap[0];
    float mu = 0.f, s2 = 0.f;
#pragma unroll 1
    for (int o = 0; o < C_; o++) {
        float acc = bp[o];
#pragma unroll
        for (int c = 0; c < C_; c++) acc += sW[o * C_ + c] * ov[c];
        acc = acc >= 0.f ? acc : a * acc;
        y[o] = acc;
        mu += acc;
        s2 += acc * acc;
    }
    mu *= (1.f / C_);
    s2 = s2 * (1.f / C_) - mu * mu;
    float inv = rsqrtf(s2 + EPS);
#pragma unroll 1
    for (int o = 0; o < C_; o++) {
        float val = (y[o] - mu) * inv * gp[o] + betap[o];
        size_t idx = ((size_t)(b * C_ + o) * T_ + t) * F_ + f;
        out[idx] = val + x[idx];
    }
}

// ============================================================================
extern "C" void kernel_launch(void* const* d_in, const int* in_sizes, int n_in,
                              void* d_out, int out_size) {
    const float* x     = (const float*)d_in[0];
    const float* Wq    = (const float*)d_in[1];
    const float* bq    = (const float*)d_in[2];
    const float* aq    = (const float*)d_in[3];
    const float* gq    = (const float*)d_in[4];
    const float* betaq = (const float*)d_in[5];
    const float* Wk    = (const float*)d_in[6];
    const float* bk    = (const float*)d_in[7];
    const float* ak    = (const float*)d_in[8];
    const float* gk    = (const float*)d_in[9];
    const float* betak = (const float*)d_in[10];
    const float* Wv    = (const float*)d_in[11];
    const float* bv    = (const float*)d_in[12];
    const float* av    = (const float*)d_in[13];
    const float* gv    = (const float*)d_in[14];
    const float* betav = (const float*)d_in[15];
    const float* Wp    = (const float*)d_in[16];
    const float* bp    = (const float*)d_in[17];
    const float* ap    = (const float*)d_in[18];
    const float* gp    = (const float*)d_in[19];
    const float* betap = (const float*)d_in[20];
    float* out = (float*)d_out;

    const int P = B_ * T_ * F_;
    k_proj<<<(P + 255) / 256, 256>>>(x, Wq, bq, aq, gq, betaq,
                                     Wk, bk, ak, gk, betak,
                                     Wv, bv, av, gv, betav);

    const float scale = 1.0f / sqrtf((float)DF);
    dim3 gqk(TNP / 128, TMPAD / 128, BH);    // 24 x 24 x 8
    k_gemm<false><<<gqk, 256>>>(scale);

    dim3 gsm(TMPAD, BH);
    k_softmax<<<gsm, 256>>>();

    dim3 gpv(NPV / 128, TMPAD / 128, BH);    // 9 x 24 x 8
    k_gemm<true><<<gpv, 256>>>(1.0f);

    k_final<<<(P + 127) / 128, 128>>>(x, Wp, bp, ap, gp, betap, out);
}

// round 4
// speedup vs baseline: 5.0344x; 1.1714x over previous
#include <cuda_runtime.h>
#include <cuda_fp16.h>
#include <math.h>
#include <cstdint>

#define B_    2
#define C_    64
#define T_    3000
#define F_    65
#define H_    4
#define D_    4
#define E_    16
#define DF    260
#define KQK   288      // QK K-dim padded (mult of 32)
#define EF    1040
#define NPV   1152     // PV N-dim padded (mult of 128)
#define KPV   3008     // PV K-dim padded (mult of 32); also P row width
#define TMPAD 3072     // M padded (mult of 128)
#define TNP   3072     // QK N tile range
#define EFO   1042     // O row width: EF cols + rowsum col (1040) + 1 pad
#define BH    8
#define EPS   1e-5f

// ---------------- scratch (zero-initialized .bss; pads rely on that + writes)
__device__ __align__(128) __half g_Qh[(size_t)BH * TMPAD * KQK];
__device__ __align__(128) __half g_Kh[(size_t)BH * TMPAD * KQK];
__device__ __align__(128) __half g_P [(size_t)BH * TMPAD * KPV];   // exp(S), unnormalized
__device__ __align__(128) __half g_Vn[(size_t)BH * KPV * NPV];     // V + ones col @1040
__device__ __align__(128) float  g_O [(size_t)BH * T_ * EFO];      // U and rowsum col

// ---------------- helpers ----------------------------------------------------
__device__ __forceinline__ uint32_t smem_u32(const void* p) {
    uint32_t a;
    asm("{ .reg .u64 t; cvta.to.shared.u64 t, %1; cvt.u32.u64 %0, t; }" : "=r"(a) : "l"(p));
    return a;
}
__device__ __forceinline__ void cpa16(uint32_t s, const void* g) {
    asm volatile("cp.async.cg.shared.global [%0], [%1], 16;" :: "r"(s), "l"(g));
}
__device__ __forceinline__ void ldm4(uint32_t* r, uint32_t a) {
    asm volatile("ldmatrix.sync.aligned.m8n8.x4.shared.b16 {%0,%1,%2,%3}, [%4];"
                 : "=r"(r[0]), "=r"(r[1]), "=r"(r[2]), "=r"(r[3]) : "r"(a));
}
__device__ __forceinline__ void ldm4t(uint32_t* r, uint32_t a) {
    asm volatile("ldmatrix.sync.aligned.m8n8.x4.trans.shared.b16 {%0,%1,%2,%3}, [%4];"
                 : "=r"(r[0]), "=r"(r[1]), "=r"(r[2]), "=r"(r[3]) : "r"(a));
}
__device__ __forceinline__ void mma16816(float* c, const uint32_t* a, const uint32_t* b) {
    asm volatile("mma.sync.aligned.m16n8k16.row.col.f32.f16.f16.f32 "
                 "{%0,%1,%2,%3}, {%4,%5,%6,%7}, {%8,%9}, {%0,%1,%2,%3};"
                 : "+f"(c[0]), "+f"(c[1]), "+f"(c[2]), "+f"(c[3])
                 : "r"(a[0]), "r"(a[1]), "r"(a[2]), "r"(a[3]), "r"(b[0]), "r"(b[1]));
}

// ============================================================================
// Kernel 1: Q/K/V 1x1-conv + PReLU + channel-LN -> fp16.
// Q,K: [bh][t][KQK] row-major (k-pad cols zeroed). V: [bh][t][NPV] natural,
// plus a ones-column at 1040 (feeds the PV GEMM's rowsum output).
// ============================================================================
__global__ void k_proj(const float* __restrict__ x,
                       const float* __restrict__ Wq, const float* __restrict__ bq,
                       const float* __restrict__ aq, const float* __restrict__ gq,
                       const float* __restrict__ betaq,
                       const float* __restrict__ Wk, const float* __restrict__ bk,
                       const float* __restrict__ ak, const float* __restrict__ gk,
                       const float* __restrict__ betak,
                       const float* __restrict__ Wv, const float* __restrict__ bv,
                       const float* __restrict__ av, const float* __restrict__ gv,
                       const float* __restrict__ betav) {
    __shared__ float sWq[H_ * D_ * C_];
    __shared__ float sWk[H_ * D_ * C_];
    __shared__ float sWv[H_ * E_ * C_];
    int tid = threadIdx.x;
    for (int i = tid; i < H_ * D_ * C_; i += blockDim.x) { sWq[i] = Wq[i]; sWk[i] = Wk[i]; }
    for (int i = tid; i < H_ * E_ * C_; i += blockDim.x) sWv[i] = Wv[i];
    __syncthreads();

    int p = blockIdx.x * blockDim.x + tid;
    const int P = B_ * T_ * F_;
    if (p >= P) return;
    int b = p / (T_ * F_);
    int r = p % (T_ * F_);
    int t = r / F_;
    int f = r % F_;

    float xv[C_];
#pragma unroll
    for (int c = 0; c < C_; c++)
        xv[c] = x[((size_t)(b * C_ + c) * T_ + t) * F_ + f];

    const __half hz = __float2half(0.0f);
    for (int h = 0; h < H_; h++) {
        int bh = b * H_ + h;
        // ---- Q ----
        {
            float q[D_];
            float ah = aq[h];
#pragma unroll
            for (int d = 0; d < D_; d++) {
                float acc = bq[h * D_ + d];
#pragma unroll
                for (int c = 0; c < C_; c++) acc += sWq[(h * D_ + d) * C_ + c] * xv[c];
                q[d] = acc >= 0.f ? acc : ah * acc;
            }
            float mu = 0.f, s2 = 0.f;
#pragma unroll
            for (int d = 0; d < D_; d++) { mu += q[d]; s2 += q[d] * q[d]; }
            mu *= (1.f / D_);
            s2 = s2 * (1.f / D_) - mu * mu;
            float inv = rsqrtf(s2 + EPS);
            size_t base = ((size_t)bh * TMPAD + t) * KQK;
#pragma unroll
            for (int d = 0; d < D_; d++)
                g_Qh[base + d * F_ + f] =
                    __float2half((q[d] - mu) * inv * gq[h * D_ + d] + betaq[h * D_ + d]);
            if (f < KQK - DF) g_Qh[base + DF + f] = hz;
        }
        // ---- K ----
        {
            float q[D_];
            float ah = ak[h];
#pragma unroll
            for (int d = 0; d < D_; d++) {
                float acc = bk[h * D_ + d];
#pragma unroll
                for (int c = 0; c < C_; c++) acc += sWk[(h * D_ + d) * C_ + c] * xv[c];
                q[d] = acc >= 0.f ? acc : ah * acc;
            }
            float mu = 0.f, s2 = 0.f;
#pragma unroll
            for (int d = 0; d < D_; d++) { mu += q[d]; s2 += q[d] * q[d]; }
            mu *= (1.f / D_);
            s2 = s2 * (1.f / D_) - mu * mu;
            float inv = rsqrtf(s2 + EPS);
            size_t base = ((size_t)bh * TMPAD + t) * KQK;
#pragma unroll
            for (int d = 0; d < D_; d++)
                g_Kh[base + d * F_ + f] =
                    __float2half((q[d] - mu) * inv * gk[h * D_ + d] + betak[h * D_ + d]);
            if (f < KQK - DF) g_Kh[base + DF + f] = hz;
        }
        // ---- V (natural layout [t][ef]) + ones column ----
        {
            float v[E_];
            float ah = av[h];
#pragma unroll
            for (int e = 0; e < E_; e++) {
                float acc = bv[h * E_ + e];
#pragma unroll
                for (int c = 0; c < C_; c++) acc += sWv[(h * E_ + e) * C_ + c] * xv[c];
                v[e] = acc >= 0.f ? acc : ah * acc;
            }
            float mu = 0.f, s2 = 0.f;
#pragma unroll
            for (int e = 0; e < E_; e++) { mu += v[e]; s2 += v[e] * v[e]; }
            mu *= (1.f / E_);
            s2 = s2 * (1.f / E_) - mu * mu;
            float inv = rsqrtf(s2 + EPS);
            size_t base = ((size_t)bh * KPV + t) * NPV;
#pragma unroll
            for (int e = 0; e < E_; e++)
                g_Vn[base + e * F_ + f] =
                    __float2half((v[e] - mu) * inv * gv[h * E_ + e] + betav[h * E_ + e]);
            if (f == 0) g_Vn[base + EF] = __float2half(1.0f);   // rowsum column
        }
    }
}

// ============================================================================
// HMMA GEMM, 3-stage cp.async pipeline, one __syncthreads per K-chunk.
//   QK (PV=false): A=Q[m][k], B=K[n][k] -> P = fp16(exp(scale*acc)), pads zeroed
//   PV (PV=true) : A=P[m][k], B=Vn[k][n] -> g_O fp32 (cols 0..1041 incl rowsum)
// CTA 128x128, BK=32, 8 warps (warp 32x64).
// ============================================================================
#define ASTG 10240
#define BSTG 10240
#define STG  (ASTG + BSTG)
#define NSTAGE 3

template <bool PV>
__global__ void __launch_bounds__(256, 2) k_gemm(float scale) {
    extern __shared__ __align__(128) char smem[];
    const int tid = threadIdx.x;
    const int wid = tid >> 5, lane = tid & 31;
    const int wm = wid & 3, wn = wid >> 2;
    const int bh = blockIdx.z, m0 = blockIdx.y * 128, n0 = blockIdx.x * 128;

    const __half *Ag, *Bg;
    int lda, chunks;
    if (PV) {
        Ag = g_P + (size_t)bh * TMPAD * KPV;  lda = KPV;
        Bg = g_Vn + (size_t)bh * KPV * NPV;   chunks = KPV / 32;
    } else {
        Ag = g_Qh + (size_t)bh * TMPAD * KQK; lda = KQK;
        Bg = g_Kh + (size_t)bh * TMPAD * KQK; chunks = KQK / 32;
    }

    const uint32_t sbase = smem_u32(smem);

    float acc[2][8][4];
#pragma unroll
    for (int i = 0; i < 2; i++)
#pragma unroll
        for (int j = 0; j < 8; j++)
#pragma unroll
            for (int q = 0; q < 4; q++) acc[i][j][q] = 0.f;

    auto load_stage = [&](int st, int c) {
        uint32_t sa = sbase + st * STG;
        uint32_t sb = sa + ASTG;
        int k0 = c * 32;
#pragma unroll
        for (int j = 0; j < 2; j++) {
            int idx = tid * 2 + j;
            {   // A tile: 128 rows x 64B (4 granules), 80B smem stride
                int row = idx >> 2, g = idx & 3;
                cpa16(sa + row * 80 + g * 16, Ag + (size_t)(m0 + row) * lda + k0 + g * 8);
            }
            if (PV) {  // B tile: 32 k-rows x 256B (16 granules), 272B stride
                int row = idx >> 4, g = idx & 15;
                cpa16(sb + row * 272 + g * 16, Bg + (size_t)(k0 + row) * NPV + n0 + g * 8);
            } else {   // B tile: 128 n-rows x 64B, 80B stride
                int row = idx >> 2, g = idx & 3;
                cpa16(sb + row * 80 + g * 16, Bg + (size_t)(n0 + row) * lda + k0 + g * 8);
            }
        }
    };

    auto compute_stage = [&](int st) {
        uint32_t sa = sbase + st * STG;
        uint32_t sb = sa + ASTG;
#pragma unroll
        for (int kk = 0; kk < 32; kk += 16) {
            uint32_t a[2][4];
#pragma unroll
            for (int mt = 0; mt < 2; mt++) {
                int row = wm * 32 + mt * 16 + (lane & 15);
                ldm4(a[mt], sa + row * 80 + (kk + ((lane >> 4) << 3)) * 2);
            }
            uint32_t bfr[4][4];
#pragma unroll
            for (int bt = 0; bt < 4; bt++) {
                if (PV) {
                    int krow = kk + (lane & 15);
                    int ncol = wn * 64 + bt * 16 + ((lane >> 4) << 3);
                    ldm4t(bfr[bt], sb + krow * 272 + ncol * 2);
                } else {
                    int row = wn * 64 + bt * 16 + ((lane >> 4) << 3) + (lane & 7);
                    ldm4(bfr[bt], sb + row * 80 + (kk + ((lane >> 3) & 1) * 8) * 2);
                }
            }
#pragma unroll
            for (int mt = 0; mt < 2; mt++)
#pragma unroll
                for (int nt = 0; nt < 8; nt++)
                    mma16816(acc[mt][nt], a[mt], &bfr[nt >> 1][(nt & 1) * 2]);
        }
    };

    // 3-stage pipeline: prologue loads stages 0,1; each iter loads c+2, computes c.
    load_stage(0, 0);
    asm volatile("cp.async.commit_group;" ::: "memory");
    load_stage(1, 1);
    asm volatile("cp.async.commit_group;" ::: "memory");

    int st = 0;
    for (int c = 0; c < chunks; c++) {
        if (c == chunks - 1) asm volatile("cp.async.wait_group 0;" ::: "memory");
        else                 asm volatile("cp.async.wait_group 1;" ::: "memory");
        __syncthreads();   // stage c ready; compute(c-1) finished by all -> (c+2)%3 reusable
        if (c + 2 < chunks) {
            int st2 = st + 2; if (st2 >= NSTAGE) st2 -= NSTAGE;
            load_stage(st2, c + 2);
            asm volatile("cp.async.commit_group;" ::: "memory");
        }
        compute_stage(st);
        if (++st == NSTAGE) st = 0;
    }

    // epilogue
#pragma unroll
    for (int mt = 0; mt < 2; mt++)
#pragma unroll
        for (int nt = 0; nt < 8; nt++) {
            int r0 = m0 + wm * 32 + mt * 16 + (lane >> 2);
            int cc = n0 + wn * 64 + nt * 8 + (lane & 3) * 2;
            float* a4 = acc[mt][nt];
            if (PV) {
                if (cc < EFO) {
                    if (r0 < T_)
                        *reinterpret_cast<float2*>(&g_O[((size_t)bh * T_ + r0) * EFO + cc]) =
                            make_float2(a4[0], a4[1]);
                    if (r0 + 8 < T_)
                        *reinterpret_cast<float2*>(&g_O[((size_t)bh * T_ + r0 + 8) * EFO + cc]) =
                            make_float2(a4[2], a4[3]);
                }
            } else {
                if (cc < KPV) {   // P cols: exp for cc<T_, zero for pad cols
                    __half2 h0, h1;
                    h0.x = (cc     < T_) ? __float2half(__expf(a4[0] * scale)) : __float2half(0.f);
                    h0.y = (cc + 1 < T_) ? __float2half(__expf(a4[1] * scale)) : __float2half(0.f);
                    h1.x = (cc     < T_) ? __float2half(__expf(a4[2] * scale)) : __float2half(0.f);
                    h1.y = (cc + 1 < T_) ? __float2half(__expf(a4[3] * scale)) : __float2half(0.f);
                    *reinterpret_cast<__half2*>(&g_P[((size_t)bh * TMPAD + r0) * KPV + cc]) = h0;
                    *reinterpret_cast<__half2*>(&g_P[((size_t)bh * TMPAD + r0 + 8) * KPV + cc]) = h1;
                }
            }
        }
}

// ============================================================================
// Kernel 3: final 1x1 conv (64x64) + PReLU + channel-LN + residual,
// with deferred softmax normalization (divide by rowsum column of g_O).
// ============================================================================
__global__ void k_final(const float* __restrict__ x,
                        const float* __restrict__ Wp, const float* __restrict__ bp,
                        const float* __restrict__ ap, const float* __restrict__ gp,
                        const float* __restrict__ betap,
                        float* __restrict__ out) {
    __shared__ float sW[C_ * C_];
    int tid = threadIdx.x;
    for (int i = tid; i < C_ * C_; i += blockDim.x) sW[i] = Wp[i];
    __syncthreads();

    int p = blockIdx.x * blockDim.x + tid;
    const int P = B_ * T_ * F_;
    if (p >= P) return;
    int b = p / (T_ * F_);
    int r = p % (T_ * F_);
    int t = r / F_;
    int f = r % F_;

    float rinv[H_];
#pragma unroll
    for (int h = 0; h < H_; h++)
        rinv[h] = 1.0f / g_O[((size_t)(b * H_ + h) * T_ + t) * EFO + EF];

    float ov[C_];
#pragma unroll
    for (int c = 0; c < C_; c++) {
        int h = c >> 4, e = c & 15;
        ov[c] = g_O[((size_t)(b * H_ + h) * T_ + t) * EFO + e * F_ + f] * rinv[h];
    }

    float y[C_];
    float a = ap[0];
    float mu = 0.f, s2 = 0.f;
#pragma unroll 1
    for (int o = 0; o < C_; o++) {
        float acc = bp[o];
#pragma unroll
        for (int c = 0; c < C_; c++) acc += sW[o * C_ + c] * ov[c];
        acc = acc >= 0.f ? acc : a * acc;
        y[o] = acc;
        mu += acc;
        s2 += acc * acc;
    }
    mu *= (1.f / C_);
    s2 = s2 * (1.f / C_) - mu * mu;
    float inv = rsqrtf(s2 + EPS);
#pragma unroll 1
    for (int o = 0; o < C_; o++) {
        float val = (y[o] - mu) * inv * gp[o] + betap[o];
        size_t idx = ((size_t)(b * C_ + o) * T_ + t) * F_ + f;
        out[idx] = val + x[idx];
    }
}

// ============================================================================
extern "C" void kernel_launch(void* const* d_in, const int* in_sizes, int n_in,
                              void* d_out, int out_size) {
    const float* x     = (const float*)d_in[0];
    const float* Wq    = (const float*)d_in[1];
    const float* bq    = (const float*)d_in[2];
    const float* aq    = (const float*)d_in[3];
    const float* gq    = (const float*)d_in[4];
    const float* betaq = (const float*)d_in[5];
    const float* Wk    = (const float*)d_in[6];
    const float* bk    = (const float*)d_in[7];
    const float* ak    = (const float*)d_in[8];
    const float* gk    = (const float*)d_in[9];
    const float* betak = (const float*)d_in[10];
    const float* Wv    = (const float*)d_in[11];
    const float* bv    = (const float*)d_in[12];
    const float* av    = (const float*)d_in[13];
    const float* gv    = (const float*)d_in[14];
    const float* betav = (const float*)d_in[15];
    const float* Wp    = (const float*)d_in[16];
    const float* bp    = (const float*)d_in[17];
    const float* ap    = (const float*)d_in[18];
    const float* gp    = (const float*)d_in[19];
    const float* betap = (const float*)d_in[20];
    float* out = (float*)d_out;

    static bool attr_set = false;
    if (!attr_set) {
        cudaFuncSetAttribute(k_gemm<false>, cudaFuncAttributeMaxDynamicSharedMemorySize,
                             NSTAGE * STG);
        cudaFuncSetAttribute(k_gemm<true>, cudaFuncAttributeMaxDynamicSharedMemorySize,
                             NSTAGE * STG);
        attr_set = true;
    }

    const int P = B_ * T_ * F_;
    k_proj<<<(P + 255) / 256, 256>>>(x, Wq, bq, aq, gq, betaq,
                                     Wk, bk, ak, gk, betak,
                                     Wv, bv, av, gv, betav);

    const float scale = 1.0f / sqrtf((float)DF);
    dim3 gqk(TNP / 128, TMPAD / 128, BH);    // 24 x 24 x 8
    k_gemm<false><<<gqk, 256, NSTAGE * STG>>>(scale);

    dim3 gpv(NPV / 128, TMPAD / 128, BH);    // 9 x 24 x 8
    k_gemm<true><<<gpv, 256, NSTAGE * STG>>>(1.0f);

    k_final<<<(P + 127) / 128, 128>>>(x, Wp, bp, ap, gp, betap, out);
}